// round 17
// baseline (speedup 1.0000x reference)
#include <cuda_runtime.h>
#include <stdint.h>

#define BB 32
#define NGT 20
#define FH 64
#define FW 100
#define AA 9
#define HW (FH*FW)      // 6400
#define TT (HW*AA)      // 57600
#define FG_K 128
#define RPN_BATCH_K 256
#define FULLM 0xffffffffu
#define SCAP 2048        // small-list capacity
#define T_FG (1u<<20)    // fg prune threshold on 23-bit m
#define T_BG (1u<<17)    // bg prune threshold on 23-bit m

typedef unsigned long long ull;

__device__ __constant__ float c_anchors[AA*4] = {
  -84.f,  -40.f,  99.f,  55.f,
 -176.f,  -88.f, 191.f, 103.f,
 -360.f, -184.f, 375.f, 199.f,
  -56.f,  -56.f,  71.f,  71.f,
 -120.f, -120.f, 135.f, 135.f,
 -248.f, -248.f, 263.f, 263.f,
  -36.f,  -80.f,  51.f,  95.f,
  -80.f, -168.f,  95.f, 183.f,
 -168.f, -344.f, 183.f, 359.f
};

// ---------------- Threefry-2x32 (20 rounds), matches JAX partitionable ----------------
__host__ __device__ __forceinline__ void tf2x32(uint32_t k0, uint32_t k1,
                                                uint32_t x0, uint32_t x1,
                                                uint32_t& o0, uint32_t& o1) {
  uint32_t ks2 = k0 ^ k1 ^ 0x1BD11BDAu;
  x0 += k0; x1 += k1;
#define TF_RND(r) { x0 += x1; x1 = (x1 << (r)) | (x1 >> (32 - (r))); x1 ^= x0; }
  TF_RND(13) TF_RND(15) TF_RND(26) TF_RND(6)   x0 += k1;  x1 += ks2 + 1u;
  TF_RND(17) TF_RND(29) TF_RND(16) TF_RND(24)  x0 += ks2; x1 += k0  + 2u;
  TF_RND(13) TF_RND(15) TF_RND(26) TF_RND(6)   x0 += k0;  x1 += k1  + 3u;
  TF_RND(17) TF_RND(29) TF_RND(16) TF_RND(24)  x0 += k1;  x1 += ks2 + 4u;
  TF_RND(13) TF_RND(15) TF_RND(26) TF_RND(6)   x0 += ks2; x1 += k0  + 5u;
#undef TF_RND
  o0 = x0; o1 = x1;
}

// ---------------- scratch (device globals; no allocations) ----------------
// g_cnt layout: [0,32)=fg  [32,64)=bg  [64,96)=sfg  [96,128)=sbg
// Invariant: all-zero at launch entry (zero-init; k3's bg blocks self-clean).
__device__ int           g_cnt[4*BB];
__device__ ull           g_cfg[(size_t)BB*TT];  // fg full candidate keys (m<<16)|t
__device__ ull           g_cbg[(size_t)BB*TT];  // bg full candidate keys
__device__ ull           g_sfg[BB*SCAP];        // fg pruned keys (m < T_FG)
__device__ ull           g_sbg[BB*SCAP];        // bg pruned keys (m < T_BG)

// max over integer shift s in [i0,i1] of the exact float axis-overlap
__device__ __forceinline__ float axis_max(float A1, float A2, float G1, float G2,
                                          int i0, int i1) {
  float p1 = (G1 - A1) * 0.0625f;
  float p2 = (G2 - A2) * 0.0625f;
  int c0 = (int)floorf(fminf(p1, p2));
  int c2 = (int)floorf(fmaxf(p1, p2));
  int cand[6] = {i0, i1, c0, c0 + 1, c2, c2 + 1};
  float best = -1e30f;
#pragma unroll
  for (int j = 0; j < 6; j++) {
    int s = min(max(cand[j], i0), i1);
    float fs = 16.f * (float)s;
    float v = __fadd_rn(__fsub_rn(fminf(A2 + fs, G2), fmaxf(A1 + fs, G1)), 1.0f);
    best = fmaxf(best, v);
  }
  return best;
}

// warp-aggregated allocation
__device__ __forceinline__ int warp_alloc(int* ctr, int cnt) {
  int lane = threadIdx.x & 31;
  int v = cnt;
#pragma unroll
  for (int o = 1; o < 32; o <<= 1) {
    int n = __shfl_up_sync(FULLM, v, o);
    if (lane >= o) v += n;
  }
  int total = __shfl_sync(FULLM, v, 31);
  int base = 0;
  if (lane == 31 && total) base = atomicAdd(ctr, total);
  base = __shfl_sync(FULLM, base, 31);
  return base + v - cnt;
}

// ---------------- K2: 4-wide: gtmax+fill+targets+labels+RNG+compaction ----------------
__global__ void __launch_bounds__(320) k2_main(
    const float* __restrict__ gt, const float* __restrict__ iminfo,
    uint32_t kf0, uint32_t kf1, uint32_t kb0, uint32_t kb1,
    float* __restrict__ out) {
  __shared__ float s_gx1[NGT], s_gy1[NGT], s_gx2[NGT], s_gy2[NGT];
  __shared__ float s_ga[NGT], s_gcx[NGT], s_gcy[NGT], s_lw[NGT], s_lh[NGT], s_gm[NGT];
  __shared__ unsigned s_gmu[NGT];
  __shared__ int s_gl[NGT];
  __shared__ int s_ng;
  int b = blockIdx.z, a = blockIdx.y, tid = threadIdx.x;
  int hw0 = (blockIdx.x * 320 + tid) * 4;

  float ax1_0 = c_anchors[a*4+0], ay1_0 = c_anchors[a*4+1];
  float ax2_0 = c_anchors[a*4+2], ay2_0 = c_anchors[a*4+3];
  float ew = __fadd_rn(__fsub_rn(ax2_0, ax1_0), 1.0f);
  float eh = __fadd_rn(__fsub_rn(ay2_0, ay1_0), 1.0f);
  float area = __fmul_rn(ew, eh);

  // ---- setup phase 0: gt prep (tid<32) + gmu zero ----
  if (tid < NGT) s_gmu[tid] = 0u;
  if (tid < 32) {
    bool nz = false;
    if (tid < NGT) {
      float x1 = gt[(b*NGT+tid)*5+0], y1 = gt[(b*NGT+tid)*5+1];
      float x2 = gt[(b*NGT+tid)*5+2], y2 = gt[(b*NGT+tid)*5+3];
      float gw = __fadd_rn(__fsub_rn(x2, x1), 1.0f);
      float gh = __fadd_rn(__fsub_rn(y2, y1), 1.0f);
      nz = !(gw == 1.0f && gh == 1.0f);
      s_gx1[tid] = x1; s_gy1[tid] = y1; s_gx2[tid] = x2; s_gy2[tid] = y2;
      s_ga[tid]  = __fmul_rn(gw, gh);
      s_gcx[tid] = x1 + 0.5f * gw;
      s_gcy[tid] = y1 + 0.5f * gh;
      s_lw[tid]  = logf(gw / ew);
      s_lh[tid]  = logf(gh / eh);
    }
    unsigned mask = __ballot_sync(FULLM, nz);
    if (tid == 0) s_ng = __popc(mask);
    if (nz) s_gl[__popc(mask & ((1u << tid) - 1u))] = tid;
  }
  __syncthreads();

  // ---- setup phase 1: analytic per-(g,a) gt-max (threads 32..211) ----
  if (tid >= 32 && tid < 32 + NGT*AA) {
    int idx = tid - 32;
    int g = idx / AA, aa = idx - g * AA;
    float gx1 = s_gx1[g], gy1 = s_gy1[g], gx2 = s_gx2[g], gy2 = s_gy2[g];
    float gw = __fadd_rn(__fsub_rn(gx2, gx1), 1.0f);
    float gh = __fadd_rn(__fsub_rn(gy2, gy1), 1.0f);
    if (!(gw == 1.0f && gh == 1.0f)) {
      float ga = __fmul_rn(gw, gh);
      float img_h = iminfo[0], img_w = iminfo[1];
      float bx1 = c_anchors[aa*4+0], by1 = c_anchors[aa*4+1];
      float bx2 = c_anchors[aa*4+2], by2 = c_anchors[aa*4+3];
      int wi0 = max((int)ceilf(-bx1 * 0.0625f), 0);
      int wi1 = min((int)floorf((img_w - 1.0f - bx2) * 0.0625f), FW-1);
      int hi0 = max((int)ceilf(-by1 * 0.0625f), 0);
      int hi1 = min((int)floorf((img_h - 1.0f - by2) * 0.0625f), FH-1);
      if (wi0 <= wi1 && hi0 <= hi1) {
        float iwb = axis_max(bx1, bx2, gx1, gx2, wi0, wi1);
        float ihb = axis_max(by1, by2, gy1, gy2, hi0, hi1);
        if (iwb > 0.0f && ihb > 0.0f) {
          float bw = __fadd_rn(__fsub_rn(bx2, bx1), 1.0f);
          float bh = __fadd_rn(__fsub_rn(by2, by1), 1.0f);
          float barea = __fmul_rn(bw, bh);
          float inter = __fmul_rn(iwb, ihb);
          float ua = __fsub_rn(__fadd_rn(barea, ga), inter);
          float v  = __fdiv_rn(inter, ua);
          atomicMax(&s_gmu[g], __float_as_uint(v) | 0x80000000u);
        }
      }
    }
  }
  __syncthreads();
  if (tid < NGT) {
    unsigned u_ = s_gmu[tid];
    s_gm[tid] = u_ ? __uint_as_float(u_ ^ 0x80000000u) : -999.0f;
  }
  __syncthreads();

  float img_h = iminfo[0], img_w = iminfo[1];
  int h = hw0 / FW, w0 = hw0 - h * FW;
  float sy = 16.f * (float)h;
  float ay1 = ay1_0 + sy, ay2 = ay2_0 + sy;
  bool iny = (ay1 >= 0.f) && (ay2 < img_h);

  float ax1[4], ax2v[4];
  bool inside[4];
  float mx[4] = {0.f, 0.f, 0.f, 0.f};
  int amax[4] = {0, 0, 0, 0};
  bool keep[4] = {false, false, false, false};
#pragma unroll
  for (int p = 0; p < 4; p++) {
    float sx = 16.f * (float)(w0 + p);
    ax1[p]  = ax1_0 + sx;
    ax2v[p] = ax2_0 + sx;
    inside[p] = iny && (ax1[p] >= 0.f) && (ax2v[p] < img_w);
  }

  int ng = s_ng;
  if (inside[0] || inside[3]) {
    for (int gi = 0; gi < ng; gi++) {
      int g = s_gl[gi];
      float ihh = __fadd_rn(__fsub_rn(fminf(ay2, s_gy2[g]), fmaxf(ay1, s_gy1[g])), 1.0f);
      ihh = fmaxf(ihh, 0.0f);
      if (ihh <= 0.0f) continue;
      float gx1 = s_gx1[g], gx2 = s_gx2[g];
      float iwmax = __fadd_rn(__fsub_rn(fminf(ax2v[3], gx2), fmaxf(ax1[0], gx1)), 1.0f);
      if (iwmax <= 0.0f) continue;
      float ga = s_ga[g], gm = s_gm[g];
#pragma unroll
      for (int p = 0; p < 4; p++) {
        if (!inside[p]) continue;
        float iw = __fadd_rn(__fsub_rn(fminf(ax2v[p], gx2), fmaxf(ax1[p], gx1)), 1.0f);
        float inter = __fmul_rn(fmaxf(iw, 0.0f), ihh);
        if (inter <= 0.0f) continue;
        float ua = __fsub_rn(__fadd_rn(area, ga), inter);
        float tmx = __fmul_rn(mx[p], ua);        // max guard
        float bua = __fmul_rn(gm, ua);           // keep band
        if (inter > tmx * 0.9999995f || fabsf(inter - bua) <= bua * 3e-7f) {
          float v = __fdiv_rn(inter, ua);
          keep[p] = keep[p] || (v == gm);
          if (v > mx[p]) { mx[p] = v; amax[p] = g; }
        }
      }
    }
  }

  int L[4];
  float4 tgp[4];
#pragma unroll
  for (int p = 0; p < 4; p++) {
    L[p] = 2;
    if (inside[p]) L[p] = (keep[p] || mx[p] >= 0.7f) ? 1 : ((mx[p] < 0.3f) ? 0 : 2);
    tgp[p] = make_float4(0.f, 0.f, 0.f, 0.f);
    if (inside[p]) {
      int am = amax[p];
      float ecx = ax1[p] + 0.5f * ew, ecy = ay1 + 0.5f * eh;
      tgp[p].x = __fdividef(s_gcx[am] - ecx, ew);
      tgp[p].y = __fdividef(s_gcy[am] - ecy, eh);
      tgp[p].z = s_lw[am];
      tgp[p].w = s_lh[am];
    }
  }

  // ---- streaming vector stores (32-bit addressing) ----
  const unsigned OFF1 = (unsigned)BB * AA * HW;
  const unsigned PL   = (unsigned)BB * 36 * HW;
  unsigned cb = ((unsigned)b * 36 + a * 4) * HW + hw0;
  float4 z4 = make_float4(0.f, 0.f, 0.f, 0.f);
  __stcs(reinterpret_cast<float4*>(&out[((unsigned)b * AA + a) * HW + hw0]),
         make_float4(-1.f, -1.f, -1.f, -1.f));
  float* tgt_o  = out + OFF1;
  float* inw_o  = out + OFF1 + PL;
  float* outw_o = out + OFF1 + 2 * PL;
  __stcs(reinterpret_cast<float4*>(&tgt_o[cb        ]), make_float4(tgp[0].x, tgp[1].x, tgp[2].x, tgp[3].x));
  __stcs(reinterpret_cast<float4*>(&tgt_o[cb +   HW ]), make_float4(tgp[0].y, tgp[1].y, tgp[2].y, tgp[3].y));
  __stcs(reinterpret_cast<float4*>(&tgt_o[cb + 2*HW ]), make_float4(tgp[0].z, tgp[1].z, tgp[2].z, tgp[3].z));
  __stcs(reinterpret_cast<float4*>(&tgt_o[cb + 3*HW ]), make_float4(tgp[0].w, tgp[1].w, tgp[2].w, tgp[3].w));
#pragma unroll
  for (int c = 0; c < 4; c++) __stcs(reinterpret_cast<float4*>(&inw_o [cb + c * HW]), z4);
#pragma unroll
  for (int c = 0; c < 4; c++) __stcs(reinterpret_cast<float4*>(&outw_o[cb + c * HW]), z4);

  // ---- RNG draws ----
  ull key[4];
  unsigned m[4];
  int cf = 0, cbg = 0, csf = 0, csb = 0;
#pragma unroll
  for (int p = 0; p < 4; p++) {
    m[p] = 0u; key[p] = 0ull;
    if (L[p] <= 1) {
      int t = (hw0 + p) * 9 + a;
      uint32_t key0 = L[p] ? kf0 : kb0, key1 = L[p] ? kf1 : kb1;
      uint32_t o0, o1;
      tf2x32(key0, key1, 0u, (uint32_t)(b * TT + t), o0, o1);
      m[p] = (o0 ^ o1) >> 9;
      key[p] = ((ull)m[p] << 16) | (unsigned)t;
      if (L[p] == 1) { cf++; if (m[p] < T_FG) csf++; }
      else           { cbg++; if (m[p] < T_BG) csb++; }
    }
  }

  // ---- warp-aggregated compaction ----
  int basef  = warp_alloc(&g_cnt[b],        cf);
  int baseb  = warp_alloc(&g_cnt[32 + b],   cbg);
  int basesf = warp_alloc(&g_cnt[64 + b],   csf);
  int basesb = warp_alloc(&g_cnt[96 + b],   csb);
#pragma unroll
  for (int p = 0; p < 4; p++) {
    if (L[p] == 1) {
      g_cfg[(size_t)b * TT + basef++] = key[p];
      if (m[p] < T_FG) { if (basesf < SCAP) g_sfg[b*SCAP + basesf] = key[p]; basesf++; }
    } else if (L[p] == 0) {
      g_cbg[(size_t)b * TT + baseb++] = key[p];
      if (m[p] < T_BG) { if (basesb < SCAP) g_sbg[b*SCAP + basesb] = key[p]; basesb++; }
    }
  }

  // PDL: allow dependent grid (k3_select) to launch as blocks complete.
  asm volatile("griddepcontrol.launch_dependents;" ::: "memory");
}

// ---------------- K3: exact k-smallest -> direct output scatter ----------------
__device__ __forceinline__ int blockInclScan(int local, int* s_wsum) {
  int lane = threadIdx.x & 31, wid = threadIdx.x >> 5;
  int v = local;
#pragma unroll
  for (int o = 1; o < 32; o <<= 1) { int n = __shfl_up_sync(FULLM, v, o); if (lane >= o) v += n; }
  if (lane == 31) s_wsum[wid] = v;
  __syncthreads();
  if (wid == 0) {
    int wv = s_wsum[lane];
#pragma unroll
    for (int o = 1; o < 32; o <<= 1) { int n = __shfl_up_sync(FULLM, wv, o); if (lane >= o) wv += n; }
    s_wsum[lane] = wv;
  }
  __syncthreads();
  return v + (wid ? s_wsum[wid-1] : 0);
}

__device__ __forceinline__ void scatter_keep(float* out, int b, int cls, float u, ull key) {
  const unsigned OFF1 = (unsigned)BB * AA * HW;
  const unsigned PL   = (unsigned)BB * 36 * HW;
  int t = (int)(key & 0xFFFFull);
  int a = t % 9, hw = t / 9;
  out[((unsigned)b * AA + a) * HW + hw] = (float)cls;
  unsigned cb = ((unsigned)b * 36 + a * 4) * HW + hw;
  float* inw_o  = out + OFF1 + PL;
  float* outw_o = out + OFF1 + 2 * PL;
  if (cls) {
#pragma unroll
    for (int c = 0; c < 4; c++) inw_o[cb + c * HW] = 1.0f;
  }
#pragma unroll
  for (int c = 0; c < 4; c++) outw_o[cb + c * HW] = u;
}

__global__ void __launch_bounds__(1024) k3_select(float* __restrict__ out) {
  __shared__ unsigned s_hist[8192];
  __shared__ int s_wsum[32];
  __shared__ int s_sel[2];
  __shared__ int s_cnt;
  int b = blockIdx.x, cls = blockIdx.y, tid = threadIdx.x;

  // PDL: wait until primary grid (k2_main) completes & its writes are visible.
  asm volatile("griddepcontrol.wait;" ::: "memory");

  int nfg = g_cnt[b], nbg = g_cnt[32 + b];
  int kept_fg = min(nfg, FG_K);
  int kbg = RPN_BATCH_K - kept_fg;
  float u = 1.0f / (float)(kept_fg + min(nbg, kbg));
  int n = cls ? nfg : nbg;
  int k = cls ? FG_K : kbg;
  int ns = cls ? g_cnt[64 + b] : g_cnt[96 + b];
  const ull* keys = (cls ? g_cfg : g_cbg) + (size_t)b * TT;

  // self-clean for next launch: each (b,cls) block read its counters above.
  __syncthreads();
  if (tid == 0) {
    if (cls) { g_cnt[b] = 0; g_cnt[64 + b] = 0; }
    else     { g_cnt[32 + b] = 0; g_cnt[96 + b] = 0; }
  }
  // NOTE: fg block reads g_cnt[32+b] (nbg) and bg block reads g_cnt[b] (nfg)
  // before any reset can land: both reads occur pre-__syncthreads in this
  // block, and cross-block visibility of the reset requires the writer block
  // to pass its own __syncthreads first; all 64 blocks are wave-1 resident
  // (64 < 148 SMs) and loads were issued at block start.

  if (n <= k) {                      // keep everything
    for (int i = tid; i < n; i += 1024) scatter_keep(out, b, cls, u, keys[i]);
    return;
  }

  // ---- fast shared-memory path ----
  const ull* src = nullptr; int nm = 0;
  if (n <= SCAP)                        { src = keys; nm = n; }
  else if (ns >= k && ns <= SCAP)       { src = (cls ? g_sfg : g_sbg) + b*SCAP; nm = ns; }
  if (src) {
    ull* sk = reinterpret_cast<ull*>(s_hist);       // 2048 * 8B
    unsigned* h4 = s_hist + 4096;                   // 4096 bins
    for (int i = tid; i < nm; i += 1024) sk[i] = src[i];
    for (int i = tid; i < 4096; i += 1024) h4[i] = 0u;
    __syncthreads();
    for (int i = tid; i < nm; i += 1024)
      atomicAdd(&h4[(unsigned)(sk[i] >> 27)], 1u);  // top 12 bits of m
    __syncthreads();
    int base = tid * 4, local = 0;
#pragma unroll
    for (int j = 0; j < 4; j++) local += (int)h4[base + j];
    int incl = blockInclScan(local, s_wsum);
    int excl = incl - local;
    if (k > excl && k <= incl) {
      int c = excl;
      for (int j = 0; j < 4; j++) {
        int hh = (int)h4[base + j];
        if (c + hh >= k) { s_sel[0] = base + j; s_sel[1] = c; break; }
        c += hh;
      }
    }
    __syncthreads();
    int selbin = s_sel[0], cum = s_sel[1];
    for (int i = tid; i < nm; i += 1024) {
      ull key = sk[i];
      int bin = (int)(key >> 27);
      if (bin < selbin) {
        scatter_keep(out, b, cls, u, key);
      } else if (bin == selbin) {
        int lr = 0;
        for (int j = 0; j < nm; j++) {
          ull kj = sk[j];
          lr += ((int)(kj >> 27) == selbin) && (kj < key);
        }
        if (cum + lr < k) scatter_keep(out, b, cls, u, key);
      }
    }
    return;
  }

  // ---- fallback: global multi-level radix select (rare) ----
  ull* s_keys = reinterpret_cast<ull*>(s_hist);
  ull prefix = 0ull;
  int kk = k, shift = 26;
  for (int lvl = 0; ; lvl++) {
    shift = 26 - 13 * lvl;
    for (int i = tid; i < 8192; i += 1024) s_hist[i] = 0u;
    __syncthreads();
    for (int i = tid; i < n; i += 1024) {
      ull key = keys[i];
      if (lvl == 0 || (key >> (shift + 13)) == prefix)
        atomicAdd(&s_hist[(unsigned)(key >> shift) & 8191u], 1u);
    }
    __syncthreads();
    {
      int base = tid * 8, local = 0;
#pragma unroll
      for (int j = 0; j < 8; j++) local += (int)s_hist[base + j];
      int incl = blockInclScan(local, s_wsum);
      int excl = incl - local;
      if (kk > excl && kk <= incl) {
        int c = excl;
        for (int j = 0; j < 8; j++) {
          int hh = (int)s_hist[base + j];
          if (c + hh >= kk) { s_sel[0] = base + j; s_sel[1] = c; break; }
          c += hh;
        }
      }
      __syncthreads();
    }
    prefix = (prefix << 13) | (unsigned)s_sel[0];
    kk -= s_sel[1];
    int bc = (int)s_hist[s_sel[0]];
    __syncthreads();
    if (bc <= 4096 || shift == 0) break;
  }
  if (tid == 0) s_cnt = 0;
  __syncthreads();
  for (int i = tid; i < n; i += 1024) {
    ull key = keys[i];
    ull hi = key >> shift;
    if (hi < prefix) scatter_keep(out, b, cls, u, key);
    else if (hi == prefix) {
      int j = atomicAdd(&s_cnt, 1);
      s_keys[j] = key;
    }
  }
  __syncthreads();
  int cnt = s_cnt;
  for (int jj = tid; jj < cnt; jj += 1024) {
    ull kj = s_keys[jj];
    int r = 0;
    for (int i = 0; i < cnt; i++) r += (s_keys[i] < kj);
    if (r < kk) scatter_keep(out, b, cls, u, kj);
  }
}

// ---------------- host ----------------
extern "C" void kernel_launch(void* const* d_in, const int* in_sizes, int n_in,
                              void* d_out, int out_size) {
  const float* gt     = (const float*)d_in[1];   // gt_boxes [32,20,5]
  const float* iminfo = (const float*)d_in[2];   // im_info [32,3]
  float* out = (float*)d_out;

  uint32_t kf0, kf1, kb0, kb1;
  tf2x32(0u, 42u, 0u, 0u, kf0, kf1);
  tf2x32(0u, 42u, 0u, 1u, kb0, kb1);

  k2_main<<<dim3(5, AA, BB), 320>>>(gt, iminfo, kf0, kf1, kb0, kb1, out);

  // k3 with Programmatic Dependent Launch: overlaps launch/prologue with k2 tail
  cudaLaunchConfig_t cfg = {};
  cfg.gridDim  = dim3(BB, 2);
  cfg.blockDim = dim3(1024);
  cudaLaunchAttribute attrs[1];
  attrs[0].id = cudaLaunchAttributeProgrammaticStreamSerialization;
  attrs[0].val.programmaticStreamSerializationAllowed = 1;
  cfg.attrs = attrs;
  cfg.numAttrs = 1;
  cudaLaunchKernelEx(&cfg, k3_select, out);
}